// round 1
// baseline (speedup 1.0000x reference)
#include <cuda_runtime.h>
#include <math.h>

// ---------------------------------------------------------------------------
// Problem constants
//   B=2, H=W=256, C=192, HEADS=6, HEAD_DIM=32, WS=8, PW=4, HIDDEN=768
//   NTOK = B*H*W = 131072 tokens
// ---------------------------------------------------------------------------
#define NTOK   131072
#define QKVLD  288      // 192 (q) + 96 (kv) per token
#define HID    768
#define ATT_SCALE 0.17677669529663688f   // 32^-0.5

// Scratch (static device allocations — no cudaMalloc allowed)
__device__ float g_xn [(size_t)NTOK * 192];   // LN output (reused for LN2)
__device__ float g_qkv[(size_t)NTOK * QKVLD]; // q | kv packed per token
__device__ float g_aw [(size_t)NTOK * 192];   // attention output
__device__ float g_x2 [(size_t)NTOK * 192];   // post-attention residual
__device__ float g_h1 [(size_t)NTOK * HID];   // gelu(fc1)
__device__ float g_h  [(size_t)NTOK * HID];   // h1 + gelu(conv)

__device__ __forceinline__ float gelu_f(float v) {
    return 0.5f * v * (1.0f + erff(v * 0.70710678118654752440f));
}

// ---------------------------------------------------------------------------
// LayerNorm: one warp per 192-wide row
// ---------------------------------------------------------------------------
__global__ __launch_bounds__(256) void ln_kernel(
    const float* __restrict__ x, const float* __restrict__ g,
    const float* __restrict__ b, float* __restrict__ out)
{
    int row  = blockIdx.x * 8 + (threadIdx.x >> 5);
    int lane = threadIdx.x & 31;
    const float* xp = x + (size_t)row * 192;
    float v[6]; float s = 0.f;
#pragma unroll
    for (int i = 0; i < 6; i++) { v[i] = xp[lane + 32*i]; s += v[i]; }
#pragma unroll
    for (int o = 16; o > 0; o >>= 1) s += __shfl_xor_sync(0xffffffffu, s, o);
    float mu = s * (1.f/192.f);
    float var = 0.f;
#pragma unroll
    for (int i = 0; i < 6; i++) { float d = v[i] - mu; var += d*d; }
#pragma unroll
    for (int o = 16; o > 0; o >>= 1) var += __shfl_xor_sync(0xffffffffu, var, o);
    float inv = rsqrtf(var * (1.f/192.f) + 1e-5f);
    float* op = out + (size_t)row * 192;
#pragma unroll
    for (int i = 0; i < 6; i++) {
        int c = lane + 32*i;
        op[c] = (v[i] - mu) * inv * g[c] + b[c];
    }
}

// ---------------------------------------------------------------------------
// Generic fp32 GEMM:  Cc[m, n] = act( A[m,:] @ W[:,n] + bias[n] ) (+ res[m,n])
// A: M x K (row-major, stride lda); W: K x N (row-major, stride ldw)
// BM=128, BN=64, BK=16, 256 threads, 8x4 microtile
// M must be a multiple of 128 (true: 131072); K a multiple of 16.
// ---------------------------------------------------------------------------
__global__ __launch_bounds__(256) void gemm_kernel(
    const float* __restrict__ A, int lda,
    const float* __restrict__ W, int ldw,
    const float* __restrict__ bias,
    float* __restrict__ Cc, int ldc,
    int N, int K,
    const float* __restrict__ res, int act)
{
    __shared__ float As[16][132];   // padded to dodge STS bank conflicts
    __shared__ float Bs[16][68];
    int tid = threadIdx.x;
    int m0 = blockIdx.y * 128;
    int n0 = blockIdx.x * 64;
    int ty = tid >> 4, tx = tid & 15;
    float acc[8][4];
#pragma unroll
    for (int i = 0; i < 8; i++)
#pragma unroll
        for (int j = 0; j < 4; j++) acc[i][j] = 0.f;

    for (int kt = 0; kt < K; kt += 16) {
#pragma unroll
        for (int l = 0; l < 2; l++) {           // A: 128x16 = 512 float4
            int li = tid + l*256;
            int m  = li >> 2;
            int kq = (li & 3) << 2;
            float4 a = *(const float4*)&A[(size_t)(m0 + m)*lda + kt + kq];
            As[kq+0][m] = a.x; As[kq+1][m] = a.y;
            As[kq+2][m] = a.z; As[kq+3][m] = a.w;
        }
        {                                        // B: 16x64 = 256 float4
            int k  = tid >> 4;
            int nq = (tid & 15) << 2;
            int n  = n0 + nq;
            float4 bv = make_float4(0.f, 0.f, 0.f, 0.f);
            if (n + 3 < N) bv = *(const float4*)&W[(size_t)(kt + k)*ldw + n];
            *(float4*)&Bs[k][nq] = bv;
        }
        __syncthreads();
#pragma unroll
        for (int k = 0; k < 16; k++) {
            float4 a0 = *(const float4*)&As[k][ty*8];
            float4 a1 = *(const float4*)&As[k][ty*8 + 4];
            float4 bb = *(const float4*)&Bs[k][tx*4];
            float ar[8] = {a0.x,a0.y,a0.z,a0.w,a1.x,a1.y,a1.z,a1.w};
            float br[4] = {bb.x,bb.y,bb.z,bb.w};
#pragma unroll
            for (int i = 0; i < 8; i++)
#pragma unroll
                for (int j = 0; j < 4; j++) acc[i][j] += ar[i]*br[j];
        }
        __syncthreads();
    }
#pragma unroll
    for (int i = 0; i < 8; i++) {
        int m = m0 + ty*8 + i;
#pragma unroll
        for (int j = 0; j < 4; j++) {
            int n = n0 + tx*4 + j;
            if (n < N) {
                float v = acc[i][j] + bias[n];
                if (act) v = gelu_f(v);
                if (res) v += res[(size_t)m*ldc + n];
                Cc[(size_t)m*ldc + n] = v;
            }
        }
    }
}

// ---------------------------------------------------------------------------
// Windowed PSA attention.  One block per 8x8 window (2048 windows).
// 384 threads = 64 q-tokens x 6 heads; softmax over 16 kv fully in registers.
// KV gather implements: kv.reshape(b,4,2,4,2,2,48).transpose(0,1,3,5,2,4,6)
//   -> K[kvtok=(p0,p1)][f] = kvlin[tok(2p0+s0, 2p1+s1)][0*48 + c]
//      with f = s0*96 + s1*48 + c ; V uses channel 48+c.
// Bias: table[((qi/2 - kp0 + 3)*7 + (qj/2 - kp1 + 3))*6 + h]
// ---------------------------------------------------------------------------
__global__ __launch_bounds__(384) void attn_kernel(
    const float* __restrict__ qkv,
    const float* __restrict__ bias_table,
    float* __restrict__ aw)
{
    __shared__ float ks[16][192];
    __shared__ float vs[16][192];
    __shared__ float bt[296];
    int w  = blockIdx.x;
    int b  = w >> 10;
    int wi = w & 1023;
    int wy = wi >> 5, wx = wi & 31;
    int gbase = b*65536 + wy*2048 + wx*8;   // token idx of window origin
    int tid = threadIdx.x;

    for (int i = tid; i < 294; i += 384) bt[i] = bias_table[i];
    for (int i = tid; i < 3072; i += 384) {
        int kt = i / 192, f = i - kt*192;
        int p0 = kt >> 2, p1 = kt & 3;
        int s0 = f / 96;
        int s1 = (f / 48) & 1;
        int c  = f % 48;
        int g  = gbase + (p0*2 + s0)*256 + (p1*2 + s1);
        const float* row = qkv + (size_t)g*QKVLD + 192;
        ks[kt][f] = row[c];
        vs[kt][f] = row[48 + c];
    }
    __syncthreads();

    int h  = tid / 64;
    int qt = tid - h*64;
    int qi = qt >> 3, qj = qt & 7;
    int g  = gbase + qi*256 + qj;
    const float* qp = qkv + (size_t)g*QKVLD + h*32;
    float q[32];
#pragma unroll
    for (int d = 0; d < 32; d += 4) {
        float4 t4 = *(const float4*)(qp + d);
        q[d]=t4.x*ATT_SCALE; q[d+1]=t4.y*ATT_SCALE;
        q[d+2]=t4.z*ATT_SCALE; q[d+3]=t4.w*ATT_SCALE;
    }
    float sc[16]; float mx = -1e30f;
    int rq0 = (qi >> 1) + 3, rq1 = (qj >> 1) + 3;
#pragma unroll
    for (int kt = 0; kt < 16; kt++) {
        const float* kr = &ks[kt][h*32];
        float s = 0.f;
#pragma unroll
        for (int d = 0; d < 32; d++) s += q[d]*kr[d];
        int rel = (rq0 - (kt >> 2))*7 + rq1 - (kt & 3);
        s += bt[rel*6 + h];
        sc[kt] = s;
        mx = fmaxf(mx, s);
    }
    float sum = 0.f;
#pragma unroll
    for (int kt = 0; kt < 16; kt++) { sc[kt] = __expf(sc[kt] - mx); sum += sc[kt]; }
    float inv = 1.f / sum;
    float o[32];
#pragma unroll
    for (int d = 0; d < 32; d++) o[d] = 0.f;
#pragma unroll
    for (int kt = 0; kt < 16; kt++) {
        float a = sc[kt]*inv;
        const float* vr = &vs[kt][h*32];
#pragma unroll
        for (int d = 0; d < 32; d++) o[d] += a*vr[d];
    }
    float* op = aw + (size_t)g*192 + h*32;
#pragma unroll
    for (int d = 0; d < 32; d += 4)
        *(float4*)(op + d) = make_float4(o[d], o[d+1], o[d+2], o[d+3]);
}

// ---------------------------------------------------------------------------
// Depthwise 5x5 conv (channel-last) + GELU + residual:
//   out = h1 + gelu(conv(h1) + dwb)
// Block: 8 tokens x 32 channel-groups (128 channels). Weights staged in smem.
// ---------------------------------------------------------------------------
__global__ __launch_bounds__(256) void dwconv_kernel(
    const float* __restrict__ h1, const float* __restrict__ wk,
    const float* __restrict__ wb, float* __restrict__ out)
{
    __shared__ float ws[25][128];
    __shared__ float bs[128];
    int cb  = blockIdx.y * 128;
    int tid = threadIdx.x;
    for (int i = tid; i < 3200; i += 256) {
        int k = i >> 7, c = i & 127;
        ws[k][c] = wk[(size_t)(cb + c)*25 + k];
    }
    if (tid < 128) bs[tid] = wb[cb + tid];
    __syncthreads();

    int tl = tid >> 5;
    int cg = tid & 31;
    int token = blockIdx.x * 8 + tl;
    int b = token >> 16;
    int p = token & 65535;
    int y = p >> 8, x0 = p & 255;
    int ch = cb + cg*4;
    float4 acc    = make_float4(0.f, 0.f, 0.f, 0.f);
    float4 center = make_float4(0.f, 0.f, 0.f, 0.f);
#pragma unroll
    for (int dy = 0; dy < 5; dy++) {
        int yy = y + dy - 2;
        bool yok = (unsigned)yy < 256u;
#pragma unroll
        for (int dx = 0; dx < 5; dx++) {
            int xc = x0 + dx - 2;
            float4 v = make_float4(0.f, 0.f, 0.f, 0.f);
            if (yok && (unsigned)xc < 256u)
                v = *(const float4*)&h1[((size_t)(b*65536 + yy*256 + xc))*HID + ch];
            if (dy == 2 && dx == 2) center = v;
            float4 wv = *(const float4*)&ws[dy*5 + dx][cg*4];
            acc.x += v.x*wv.x; acc.y += v.y*wv.y;
            acc.z += v.z*wv.z; acc.w += v.w*wv.w;
        }
    }
    float4 bb = *(const float4*)&bs[cg*4];
    float4 r;
    r.x = center.x + gelu_f(acc.x + bb.x);
    r.y = center.y + gelu_f(acc.y + bb.y);
    r.z = center.z + gelu_f(acc.z + bb.z);
    r.w = center.w + gelu_f(acc.w + bb.w);
    *(float4*)&out[(size_t)token*HID + ch] = r;
}

// ---------------------------------------------------------------------------
// Launch sequence (graph-capturable: kernel launches only)
// ---------------------------------------------------------------------------
extern "C" void kernel_launch(void* const* d_in, const int* in_sizes, int n_in,
                              void* d_out, int out_size)
{
    const float* x    = (const float*)d_in[0];
    const float* g1   = (const float*)d_in[1];
    const float* be1  = (const float*)d_in[2];
    const float* wq   = (const float*)d_in[3];
    const float* bq   = (const float*)d_in[4];
    const float* wkv  = (const float*)d_in[5];
    const float* bkv  = (const float*)d_in[6];
    const float* btab = (const float*)d_in[7];
    const float* wproj= (const float*)d_in[8];
    const float* bproj= (const float*)d_in[9];
    const float* g2   = (const float*)d_in[10];
    const float* be2  = (const float*)d_in[11];
    const float* w1f  = (const float*)d_in[12];
    const float* b1f  = (const float*)d_in[13];
    const float* dwk  = (const float*)d_in[14];
    const float* dwb  = (const float*)d_in[15];
    const float* w2f  = (const float*)d_in[16];
    const float* b2f  = (const float*)d_in[17];
    float* out = (float*)d_out;

    float *xn, *qkv, *aw, *x2, *h1, *h;
    cudaGetSymbolAddress((void**)&xn,  g_xn);
    cudaGetSymbolAddress((void**)&qkv, g_qkv);
    cudaGetSymbolAddress((void**)&aw,  g_aw);
    cudaGetSymbolAddress((void**)&x2,  g_x2);
    cudaGetSymbolAddress((void**)&h1,  g_h1);
    cudaGetSymbolAddress((void**)&h,   g_h);

    // 1. LN1
    ln_kernel<<<NTOK/8, 256>>>(x, g1, be1, xn);
    // 2. Q = xn @ wq + bq  (into qkv cols [0,192), ldc=288)
    gemm_kernel<<<dim3(3, NTOK/128), 256>>>(xn, 192, wq, 192, bq, qkv, QKVLD,
                                            192, 192, nullptr, 0);
    // 3. KV = xn @ wkv + bkv  (into qkv cols [192,288))
    gemm_kernel<<<dim3(2, NTOK/128), 256>>>(xn, 192, wkv, 96, bkv, qkv + 192, QKVLD,
                                            96, 192, nullptr, 0);
    // 4. Window attention -> aw (token order)
    attn_kernel<<<2048, 384>>>(qkv, btab, aw);
    // 5. x2 = aw @ wproj + bproj + x
    gemm_kernel<<<dim3(3, NTOK/128), 256>>>(aw, 192, wproj, 192, bproj, x2, 192,
                                            192, 192, x, 0);
    // 6. LN2
    ln_kernel<<<NTOK/8, 256>>>(x2, g2, be2, xn);
    // 7. h1 = gelu(xn @ w1f + b1f)
    gemm_kernel<<<dim3(12, NTOK/128), 256>>>(xn, 192, w1f, HID, b1f, h1, HID,
                                             HID, 192, nullptr, 1);
    // 8. h = h1 + gelu(dwconv(h1) + dwb)
    dwconv_kernel<<<dim3(NTOK/8, 6), 256>>>(h1, dwk, dwb, h);
    // 9. out = h @ w2f + b2f + x2
    gemm_kernel<<<dim3(3, NTOK/128), 256>>>(h, HID, w2f, 192, b2f, out, 192,
                                            192, HID, x2, 0);
}

// round 2
// speedup vs baseline: 1.1215x; 1.1215x over previous
#include <cuda_runtime.h>
#include <math.h>

// ---------------------------------------------------------------------------
// Problem constants
//   B=2, H=W=256, C=192, HEADS=6, HEAD_DIM=32, WS=8, PW=4, HIDDEN=768
//   NTOK = B*H*W = 131072 tokens
// ---------------------------------------------------------------------------
#define NTOK   131072
#define QKVLD  288      // 192 (q) + 96 (kv) per token
#define HID    768
#define ATT_SCALE 0.17677669529663688f   // 32^-0.5

// Scratch (static device allocations — no cudaMalloc allowed)
__device__ float g_xn [(size_t)NTOK * 192];   // LN output (reused for LN2)
__device__ float g_qkv[(size_t)NTOK * QKVLD]; // q | kv packed per token
__device__ float g_aw [(size_t)NTOK * 192];   // attention output
__device__ float g_x2 [(size_t)NTOK * 192];   // post-attention residual
__device__ float g_h1 [(size_t)NTOK * HID];   // gelu(fc1)
__device__ float g_h  [(size_t)NTOK * HID];   // h1 + gelu(conv)

__device__ __forceinline__ float gelu_f(float v) {
    return 0.5f * v * (1.0f + erff(v * 0.70710678118654752440f));
}

__device__ __forceinline__ unsigned to_tf32(float x) {
    unsigned r;
    asm("cvt.rna.tf32.f32 %0, %1;" : "=r"(r) : "f"(x));
    return r;
}

// ---------------------------------------------------------------------------
// LayerNorm: one warp per 192-wide row
// ---------------------------------------------------------------------------
__global__ __launch_bounds__(256) void ln_kernel(
    const float* __restrict__ x, const float* __restrict__ g,
    const float* __restrict__ b, float* __restrict__ out)
{
    int row  = blockIdx.x * 8 + (threadIdx.x >> 5);
    int lane = threadIdx.x & 31;
    const float* xp = x + (size_t)row * 192;
    float v[6]; float s = 0.f;
#pragma unroll
    for (int i = 0; i < 6; i++) { v[i] = xp[lane + 32*i]; s += v[i]; }
#pragma unroll
    for (int o = 16; o > 0; o >>= 1) s += __shfl_xor_sync(0xffffffffu, s, o);
    float mu = s * (1.f/192.f);
    float var = 0.f;
#pragma unroll
    for (int i = 0; i < 6; i++) { float d = v[i] - mu; var += d*d; }
#pragma unroll
    for (int o = 16; o > 0; o >>= 1) var += __shfl_xor_sync(0xffffffffu, var, o);
    float inv = rsqrtf(var * (1.f/192.f) + 1e-5f);
    float* op = out + (size_t)row * 192;
#pragma unroll
    for (int i = 0; i < 6; i++) {
        int c = lane + 32*i;
        op[c] = (v[i] - mu) * inv * g[c] + b[c];
    }
}

// ---------------------------------------------------------------------------
// tf32 tensor-core GEMM:  C[m,n] = act( A[m,:] @ W[:,n] + bias[n] ) (+ res)
// A: M x K (row-major, lda); W: K x N (row-major, ldw)
// BM=256, BN=64, BK=32; 256 threads = 8 warps; warp tile 64x32 via
// mma.sync.aligned.m16n8k8 tf32. M % 256 == 0, K % 32 == 0.
// Smem strides 36 / 68 give conflict-free fragment LDS:
//   A bank = (4g + c) mod 32, B bank = (4c + g) mod 32 — both bijective.
// ---------------------------------------------------------------------------
__global__ __launch_bounds__(256) void gemm_tf32_kernel(
    const float* __restrict__ A, int lda,
    const float* __restrict__ W, int ldw,
    const float* __restrict__ bias,
    float* __restrict__ Cc, int ldc,
    int N, int K,
    const float* __restrict__ res, int act)
{
    __shared__ unsigned As[256 * 36];
    __shared__ unsigned Bs[32 * 68];
    int tid  = threadIdx.x;
    int lane = tid & 31;
    int warp = tid >> 5;
    int wm0 = (warp >> 1) * 64;
    int wn0 = (warp & 1) * 32;
    int g  = lane >> 2;     // group id (0..7)
    int cq = lane & 3;      // thread-in-group (0..3)
    int m0 = blockIdx.y * 256;
    int n0 = blockIdx.x * 64;

    float acc[4][4][4];
#pragma unroll
    for (int mt = 0; mt < 4; mt++)
#pragma unroll
        for (int nt = 0; nt < 4; nt++)
#pragma unroll
            for (int r = 0; r < 4; r++) acc[mt][nt][r] = 0.f;

    for (int kt = 0; kt < K; kt += 32) {
        // -------- A tile: 256x32 -> As[m][k], stride 36 --------
#pragma unroll
        for (int i = 0; i < 8; i++) {
            int idx = tid + i * 256;
            int r   = idx >> 3;
            int kq  = (idx & 7) << 2;
            float4 a = *(const float4*)&A[(size_t)(m0 + r) * lda + kt + kq];
            uint4 t;
            t.x = to_tf32(a.x); t.y = to_tf32(a.y);
            t.z = to_tf32(a.z); t.w = to_tf32(a.w);
            *(uint4*)&As[r * 36 + kq] = t;
        }
        // -------- B tile: 32x64 -> Bs[k][n], stride 68 --------
#pragma unroll
        for (int i = 0; i < 2; i++) {
            int idx = tid + i * 256;
            int kr  = idx >> 4;
            int nq  = (idx & 15) << 2;
            int n   = n0 + nq;
            float4 b = make_float4(0.f, 0.f, 0.f, 0.f);
            if (n + 3 < N) b = *(const float4*)&W[(size_t)(kt + kr) * ldw + n];
            uint4 t;
            t.x = to_tf32(b.x); t.y = to_tf32(b.y);
            t.z = to_tf32(b.z); t.w = to_tf32(b.w);
            *(uint4*)&Bs[kr * 68 + nq] = t;
        }
        __syncthreads();

#pragma unroll
        for (int s = 0; s < 4; s++) {
            unsigned a[4][4], b[4][2];
            int kb = s * 8 + cq;
#pragma unroll
            for (int mt = 0; mt < 4; mt++) {
                int rb = wm0 + mt * 16 + g;
                a[mt][0] = As[rb * 36 + kb];
                a[mt][1] = As[(rb + 8) * 36 + kb];
                a[mt][2] = As[rb * 36 + kb + 4];
                a[mt][3] = As[(rb + 8) * 36 + kb + 4];
            }
#pragma unroll
            for (int nt = 0; nt < 4; nt++) {
                int nb = wn0 + nt * 8 + g;
                b[nt][0] = Bs[kb * 68 + nb];
                b[nt][1] = Bs[(kb + 4) * 68 + nb];
            }
#pragma unroll
            for (int mt = 0; mt < 4; mt++)
#pragma unroll
                for (int nt = 0; nt < 4; nt++)
                    asm volatile(
                        "mma.sync.aligned.m16n8k8.row.col.f32.tf32.tf32.f32 "
                        "{%0,%1,%2,%3}, {%4,%5,%6,%7}, {%8,%9}, {%0,%1,%2,%3};"
                        : "+f"(acc[mt][nt][0]), "+f"(acc[mt][nt][1]),
                          "+f"(acc[mt][nt][2]), "+f"(acc[mt][nt][3])
                        : "r"(a[mt][0]), "r"(a[mt][1]), "r"(a[mt][2]), "r"(a[mt][3]),
                          "r"(b[nt][0]), "r"(b[nt][1]));
        }
        __syncthreads();
    }

    // -------- epilogue: bias (+gelu) (+residual) --------
#pragma unroll
    for (int mt = 0; mt < 4; mt++) {
        int row0 = m0 + wm0 + mt * 16 + g;
#pragma unroll
        for (int nt = 0; nt < 4; nt++) {
            int col = n0 + wn0 + nt * 8 + cq * 2;
            if (col < N) {
                float b0 = bias[col], b1 = bias[col + 1];
#pragma unroll
                for (int hh = 0; hh < 2; hh++) {
                    int row = row0 + 8 * hh;
                    float v0 = acc[mt][nt][hh * 2 + 0] + b0;
                    float v1 = acc[mt][nt][hh * 2 + 1] + b1;
                    if (act) { v0 = gelu_f(v0); v1 = gelu_f(v1); }
                    if (res) {
                        float2 rr = *(const float2*)&res[(size_t)row * ldc + col];
                        v0 += rr.x; v1 += rr.y;
                    }
                    *(float2*)&Cc[(size_t)row * ldc + col] = make_float2(v0, v1);
                }
            }
        }
    }
}

// ---------------------------------------------------------------------------
// Windowed PSA attention.  One block per 8x8 window (2048 windows).
// 384 threads = 64 q-tokens x 6 heads; softmax over 16 kv fully in registers.
// ---------------------------------------------------------------------------
__global__ __launch_bounds__(384) void attn_kernel(
    const float* __restrict__ qkv,
    const float* __restrict__ bias_table,
    float* __restrict__ aw)
{
    __shared__ float ks[16][192];
    __shared__ float vs[16][192];
    __shared__ float bt[296];
    int w  = blockIdx.x;
    int b  = w >> 10;
    int wi = w & 1023;
    int wy = wi >> 5, wx = wi & 31;
    int gbase = b*65536 + wy*2048 + wx*8;   // token idx of window origin
    int tid = threadIdx.x;

    for (int i = tid; i < 294; i += 384) bt[i] = bias_table[i];
    for (int i = tid; i < 3072; i += 384) {
        int kt = i / 192, f = i - kt*192;
        int p0 = kt >> 2, p1 = kt & 3;
        int s0 = f / 96;
        int s1 = (f / 48) & 1;
        int c  = f % 48;
        int g  = gbase + (p0*2 + s0)*256 + (p1*2 + s1);
        const float* row = qkv + (size_t)g*QKVLD + 192;
        ks[kt][f] = row[c];
        vs[kt][f] = row[48 + c];
    }
    __syncthreads();

    int h  = tid / 64;
    int qt = tid - h*64;
    int qi = qt >> 3, qj = qt & 7;
    int g  = gbase + qi*256 + qj;
    const float* qp = qkv + (size_t)g*QKVLD + h*32;
    float q[32];
#pragma unroll
    for (int d = 0; d < 32; d += 4) {
        float4 t4 = *(const float4*)(qp + d);
        q[d]=t4.x*ATT_SCALE; q[d+1]=t4.y*ATT_SCALE;
        q[d+2]=t4.z*ATT_SCALE; q[d+3]=t4.w*ATT_SCALE;
    }
    float sc[16]; float mx = -1e30f;
    int rq0 = (qi >> 1) + 3, rq1 = (qj >> 1) + 3;
#pragma unroll
    for (int kt = 0; kt < 16; kt++) {
        const float* kr = &ks[kt][h*32];
        float s = 0.f;
#pragma unroll
        for (int d = 0; d < 32; d++) s += q[d]*kr[d];
        int rel = (rq0 - (kt >> 2))*7 + rq1 - (kt & 3);
        s += bt[rel*6 + h];
        sc[kt] = s;
        mx = fmaxf(mx, s);
    }
    float sum = 0.f;
#pragma unroll
    for (int kt = 0; kt < 16; kt++) { sc[kt] = __expf(sc[kt] - mx); sum += sc[kt]; }
    float inv = 1.f / sum;
    float o[32];
#pragma unroll
    for (int d = 0; d < 32; d++) o[d] = 0.f;
#pragma unroll
    for (int kt = 0; kt < 16; kt++) {
        float a = sc[kt]*inv;
        const float* vr = &vs[kt][h*32];
#pragma unroll
        for (int d = 0; d < 32; d++) o[d] += a*vr[d];
    }
    float* op = aw + (size_t)g*192 + h*32;
#pragma unroll
    for (int d = 0; d < 32; d += 4)
        *(float4*)(op + d) = make_float4(o[d], o[d+1], o[d+2], o[d+3]);
}

// ---------------------------------------------------------------------------
// Depthwise 5x5 conv (channel-last) + GELU + residual:
//   out = h1 + gelu(conv(h1) + dwb)
// ---------------------------------------------------------------------------
__global__ __launch_bounds__(256) void dwconv_kernel(
    const float* __restrict__ h1, const float* __restrict__ wk,
    const float* __restrict__ wb, float* __restrict__ out)
{
    __shared__ float ws[25][128];
    __shared__ float bs[128];
    int cb  = blockIdx.y * 128;
    int tid = threadIdx.x;
    for (int i = tid; i < 3200; i += 256) {
        int k = i >> 7, c = i & 127;
        ws[k][c] = wk[(size_t)(cb + c)*25 + k];
    }
    if (tid < 128) bs[tid] = wb[cb + tid];
    __syncthreads();

    int tl = tid >> 5;
    int cg = tid & 31;
    int token = blockIdx.x * 8 + tl;
    int b = token >> 16;
    int p = token & 65535;
    int y = p >> 8, x0 = p & 255;
    int ch = cb + cg*4;
    float4 acc    = make_float4(0.f, 0.f, 0.f, 0.f);
    float4 center = make_float4(0.f, 0.f, 0.f, 0.f);
#pragma unroll
    for (int dy = 0; dy < 5; dy++) {
        int yy = y + dy - 2;
        bool yok = (unsigned)yy < 256u;
#pragma unroll
        for (int dx = 0; dx < 5; dx++) {
            int xc = x0 + dx - 2;
            float4 v = make_float4(0.f, 0.f, 0.f, 0.f);
            if (yok && (unsigned)xc < 256u)
                v = *(const float4*)&h1[((size_t)(b*65536 + yy*256 + xc))*HID + ch];
            if (dy == 2 && dx == 2) center = v;
            float4 wv = *(const float4*)&ws[dy*5 + dx][cg*4];
            acc.x += v.x*wv.x; acc.y += v.y*wv.y;
            acc.z += v.z*wv.z; acc.w += v.w*wv.w;
        }
    }
    float4 bb = *(const float4*)&bs[cg*4];
    float4 r;
    r.x = center.x + gelu_f(acc.x + bb.x);
    r.y = center.y + gelu_f(acc.y + bb.y);
    r.z = center.z + gelu_f(acc.z + bb.z);
    r.w = center.w + gelu_f(acc.w + bb.w);
    *(float4*)&out[(size_t)token*HID + ch] = r;
}

// ---------------------------------------------------------------------------
// Launch sequence (graph-capturable: kernel launches only)
// ---------------------------------------------------------------------------
extern "C" void kernel_launch(void* const* d_in, const int* in_sizes, int n_in,
                              void* d_out, int out_size)
{
    const float* x    = (const float*)d_in[0];
    const float* g1   = (const float*)d_in[1];
    const float* be1  = (const float*)d_in[2];
    const float* wq   = (const float*)d_in[3];
    const float* bq   = (const float*)d_in[4];
    const float* wkv  = (const float*)d_in[5];
    const float* bkv  = (const float*)d_in[6];
    const float* btab = (const float*)d_in[7];
    const float* wproj= (const float*)d_in[8];
    const float* bproj= (const float*)d_in[9];
    const float* g2   = (const float*)d_in[10];
    const float* be2  = (const float*)d_in[11];
    const float* w1f  = (const float*)d_in[12];
    const float* b1f  = (const float*)d_in[13];
    const float* dwk  = (const float*)d_in[14];
    const float* dwb  = (const float*)d_in[15];
    const float* w2f  = (const float*)d_in[16];
    const float* b2f  = (const float*)d_in[17];
    float* out = (float*)d_out;

    float *xn, *qkv, *aw, *x2, *h1, *h;
    cudaGetSymbolAddress((void**)&xn,  g_xn);
    cudaGetSymbolAddress((void**)&qkv, g_qkv);
    cudaGetSymbolAddress((void**)&aw,  g_aw);
    cudaGetSymbolAddress((void**)&x2,  g_x2);
    cudaGetSymbolAddress((void**)&h1,  g_h1);
    cudaGetSymbolAddress((void**)&h,   g_h);

    // 1. LN1
    ln_kernel<<<NTOK/8, 256>>>(x, g1, be1, xn);
    // 2. Q = xn @ wq + bq  (into qkv cols [0,192), ldc=288)
    gemm_tf32_kernel<<<dim3(3, NTOK/256), 256>>>(xn, 192, wq, 192, bq, qkv, QKVLD,
                                                 192, 192, nullptr, 0);
    // 3. KV = xn @ wkv + bkv  (into qkv cols [192,288))
    gemm_tf32_kernel<<<dim3(2, NTOK/256), 256>>>(xn, 192, wkv, 96, bkv, qkv + 192, QKVLD,
                                                 96, 192, nullptr, 0);
    // 4. Window attention -> aw (token order)
    attn_kernel<<<2048, 384>>>(qkv, btab, aw);
    // 5. x2 = aw @ wproj + bproj + x
    gemm_tf32_kernel<<<dim3(3, NTOK/256), 256>>>(aw, 192, wproj, 192, bproj, x2, 192,
                                                 192, 192, x, 0);
    // 6. LN2
    ln_kernel<<<NTOK/8, 256>>>(x2, g2, be2, xn);
    // 7. h1 = gelu(xn @ w1f + b1f)
    gemm_tf32_kernel<<<dim3(12, NTOK/256), 256>>>(xn, 192, w1f, HID, b1f, h1, HID,
                                                  HID, 192, nullptr, 1);
    // 8. h = h1 + gelu(dwconv(h1) + dwb)
    dwconv_kernel<<<dim3(NTOK/8, 6), 256>>>(h1, dwk, dwb, h);
    // 9. out = h @ w2f + b2f + x2
    gemm_tf32_kernel<<<dim3(3, NTOK/256), 256>>>(h, HID, w2f, 192, b2f, out, 192,
                                                 192, HID, x2, 0);
}

// round 5
// speedup vs baseline: 2.3589x; 2.1033x over previous
#include <cuda_runtime.h>
#include <cuda_bf16.h>
#include <cstdint>
#include <math.h>

// ---------------------------------------------------------------------------
// Problem constants
//   B=2, H=W=256, C=192, HEADS=6, HEAD_DIM=32, WS=8, PW=4, HIDDEN=768
//   NTOK = B*H*W = 131072 tokens
// ---------------------------------------------------------------------------
#define NTOK   131072
#define QKVLD  288      // 192 (q) + 96 (kv) per token, fp32
#define HID    768
#define ATT_SCALE 0.17677669529663688f   // 32^-0.5

// Scratch (static device allocations — no cudaMalloc allowed)
__device__ __align__(16) __nv_bfloat16 g_xn [(size_t)NTOK * 192];  // LN out
__device__ __align__(16) float         g_qkv[(size_t)NTOK * QKVLD];
__device__ __align__(16) __nv_bfloat16 g_aw [(size_t)NTOK * 192];  // attn out
__device__ __align__(16) float         g_x2 [(size_t)NTOK * 192];  // resid
__device__ __align__(16) __nv_bfloat16 g_h1 [(size_t)NTOK * HID];  // gelu(fc1)
__device__ __align__(16) __nv_bfloat16 g_h  [(size_t)NTOK * HID];  // ffn hidden
// bf16 weights: wq | wkv | wproj | w1f | w2f
#define WB_WQ    0
#define WB_WKV   36864
#define WB_WPROJ 55296
#define WB_W1F   92160
#define WB_W2F   239616
__device__ __align__(16) __nv_bfloat16 g_wb[387072];

__device__ __forceinline__ float gelu_f(float v) {
    return 0.5f * v * (1.0f + erff(v * 0.70710678118654752440f));
}

// ---------------------------------------------------------------------------
// fp32 -> bf16 convert (weights)
// ---------------------------------------------------------------------------
__global__ __launch_bounds__(256) void f2b_kernel(
    const float* __restrict__ s, __nv_bfloat16* __restrict__ d, int n)
{
    int i = blockIdx.x * 256 + threadIdx.x;
    if (i < n) d[i] = __float2bfloat16(s[i]);
}

// ---------------------------------------------------------------------------
// LayerNorm: one warp per 192-wide row, bf16 output
// ---------------------------------------------------------------------------
__global__ __launch_bounds__(256) void ln_kernel(
    const float* __restrict__ x, const float* __restrict__ g,
    const float* __restrict__ b, __nv_bfloat16* __restrict__ out)
{
    int row  = blockIdx.x * 8 + (threadIdx.x >> 5);
    int lane = threadIdx.x & 31;
    const float* xp = x + (size_t)row * 192;
    float v[6]; float s = 0.f;
#pragma unroll
    for (int i = 0; i < 6; i++) { v[i] = xp[lane + 32*i]; s += v[i]; }
#pragma unroll
    for (int o = 16; o > 0; o >>= 1) s += __shfl_xor_sync(0xffffffffu, s, o);
    float mu = s * (1.f/192.f);
    float var = 0.f;
#pragma unroll
    for (int i = 0; i < 6; i++) { float d = v[i] - mu; var += d*d; }
#pragma unroll
    for (int o = 16; o > 0; o >>= 1) var += __shfl_xor_sync(0xffffffffu, var, o);
    float inv = rsqrtf(var * (1.f/192.f) + 1e-5f);
    __nv_bfloat16* op = out + (size_t)row * 192;
#pragma unroll
    for (int i = 0; i < 6; i++) {
        int c = lane + 32*i;
        op[c] = __float2bfloat16((v[i] - mu) * inv * g[c] + b[c]);
    }
}

// ---------------------------------------------------------------------------
// bf16 tensor-core GEMM with cp.async double buffering + ldmatrix.
//   C[m,n] = act( A[m,:] @ W[:,n] + bias[n] ) (+ res[m,n])
// A: M x K bf16 (row-major, lda); W: K x N bf16 (row-major, ldw)
// BM=128, BN=64, BK=32; 256 threads = 8 warps (4m x 2n), warp tile 32x32.
// M % 128 == 0, K % 32 == 0, N % 8 == 0.
// ---------------------------------------------------------------------------
__device__ __forceinline__ void cp16(uint32_t dst, const void* src, bool ok) {
    int sz = ok ? 16 : 0;
    asm volatile("cp.async.cg.shared.global [%0], [%1], 16, %2;\n"
                 :: "r"(dst), "l"(src), "r"(sz));
}
__device__ __forceinline__ void ldmx4(unsigned r[4], uint32_t addr) {
    asm volatile("ldmatrix.sync.aligned.m8n8.x4.shared.b16 {%0,%1,%2,%3}, [%4];"
                 : "=r"(r[0]), "=r"(r[1]), "=r"(r[2]), "=r"(r[3]) : "r"(addr));
}
__device__ __forceinline__ void ldmx4t(unsigned r[4], uint32_t addr) {
    asm volatile("ldmatrix.sync.aligned.m8n8.x4.trans.shared.b16 {%0,%1,%2,%3}, [%4];"
                 : "=r"(r[0]), "=r"(r[1]), "=r"(r[2]), "=r"(r[3]) : "r"(addr));
}
__device__ __forceinline__ void mma_bf16(float c[4], const unsigned a[4],
                                         unsigned b0, unsigned b1) {
    asm volatile(
        "mma.sync.aligned.m16n8k16.row.col.f32.bf16.bf16.f32 "
        "{%0,%1,%2,%3}, {%4,%5,%6,%7}, {%8,%9}, {%0,%1,%2,%3};"
        : "+f"(c[0]), "+f"(c[1]), "+f"(c[2]), "+f"(c[3])
        : "r"(a[0]), "r"(a[1]), "r"(a[2]), "r"(a[3]), "r"(b0), "r"(b1));
}

#define SA 40
#define SB 72

__global__ __launch_bounds__(256) void gemm_bf16_kernel(
    const __nv_bfloat16* __restrict__ A, int lda,
    const __nv_bfloat16* __restrict__ W, int ldw,
    const float* __restrict__ bias,
    void* __restrict__ Cc, int ldc,
    int N, int K,
    const float* __restrict__ res, int act, int out_bf16)
{
    __shared__ __align__(16) __nv_bfloat16 As[2][128 * SA];
    __shared__ __align__(16) __nv_bfloat16 Bs[2][32 * SB];
    int tid  = threadIdx.x;
    int lane = tid & 31;
    int warp = tid >> 5;
    int m0 = blockIdx.y * 128;
    int n0 = blockIdx.x * 64;
    int wm0 = (warp >> 1) * 32;
    int wn0 = (warp & 1) * 32;
    int g  = lane >> 2, cq = lane & 3;
    int ln15 = lane & 15, hi8 = (lane >> 4) << 3;

    uint32_t sAb[2], sBb[2];
    sAb[0] = (uint32_t)__cvta_generic_to_shared(&As[0][0]);
    sAb[1] = (uint32_t)__cvta_generic_to_shared(&As[1][0]);
    sBb[0] = (uint32_t)__cvta_generic_to_shared(&Bs[0][0]);
    sBb[1] = (uint32_t)__cvta_generic_to_shared(&Bs[1][0]);

    float acc[2][4][4];
#pragma unroll
    for (int mt = 0; mt < 2; mt++)
#pragma unroll
        for (int nt = 0; nt < 4; nt++)
#pragma unroll
            for (int r = 0; r < 4; r++) acc[mt][nt][r] = 0.f;

    // Loader lane assignments (fixed per thread)
    int a_r0 = tid >> 2,          a_c  = (tid & 3) << 3;     // +64 rows for i=1
    int b_kr = tid >> 3,          b_nq = (tid & 7) << 3;
    bool b_ok = (n0 + b_nq + 8) <= N;

    int T = K >> 5;
    // ---- prologue: load tile 0 into stage 0 ----
    {
        cp16(sAb[0] + (a_r0 * SA + a_c) * 2,
             A + (size_t)(m0 + a_r0) * lda + a_c, true);
        cp16(sAb[0] + ((a_r0 + 64) * SA + a_c) * 2,
             A + (size_t)(m0 + a_r0 + 64) * lda + a_c, true);
        cp16(sBb[0] + (b_kr * SB + b_nq) * 2,
             b_ok ? (const void*)(W + (size_t)b_kr * ldw + n0 + b_nq) : (const void*)W, b_ok);
        asm volatile("cp.async.commit_group;\n");
    }

    for (int t = 0; t < T; t++) {
        int cur = t & 1;
        if (t + 1 < T) {
            int nxt = cur ^ 1;
            int kt  = (t + 1) << 5;
            cp16(sAb[nxt] + (a_r0 * SA + a_c) * 2,
                 A + (size_t)(m0 + a_r0) * lda + kt + a_c, true);
            cp16(sAb[nxt] + ((a_r0 + 64) * SA + a_c) * 2,
                 A + (size_t)(m0 + a_r0 + 64) * lda + kt + a_c, true);
            cp16(sBb[nxt] + (b_kr * SB + b_nq) * 2,
                 b_ok ? (const void*)(W + (size_t)(kt + b_kr) * ldw + n0 + b_nq)
                      : (const void*)W, b_ok);
            asm volatile("cp.async.commit_group;\n");
            asm volatile("cp.async.wait_group 1;\n");
        } else {
            asm volatile("cp.async.wait_group 0;\n");
        }
        __syncthreads();

        uint32_t ab = sAb[cur], bb = sBb[cur];
#pragma unroll
        for (int kb = 0; kb < 32; kb += 16) {
            unsigned af[2][4], bf[2][4];
#pragma unroll
            for (int mt = 0; mt < 2; mt++)
                ldmx4(af[mt], ab + ((wm0 + mt*16 + ln15) * SA + kb + hi8) * 2);
#pragma unroll
            for (int np = 0; np < 2; np++)
                ldmx4t(bf[np], bb + ((kb + ln15) * SB + wn0 + np*16 + hi8) * 2);
#pragma unroll
            for (int mt = 0; mt < 2; mt++)
#pragma unroll
                for (int nt = 0; nt < 4; nt++)
                    mma_bf16(acc[mt][nt], af[mt],
                             bf[nt >> 1][(nt & 1) * 2],
                             bf[nt >> 1][(nt & 1) * 2 + 1]);
        }
        __syncthreads();
    }

    // -------- epilogue: bias (+gelu) (+residual), fp32 or bf16 out --------
#pragma unroll
    for (int mt = 0; mt < 2; mt++) {
        int row0 = m0 + wm0 + mt * 16 + g;
#pragma unroll
        for (int nt = 0; nt < 4; nt++) {
            int col = n0 + wn0 + nt * 8 + cq * 2;
            if (col < N) {
                float b0 = bias[col], b1 = bias[col + 1];
#pragma unroll
                for (int hh = 0; hh < 2; hh++) {
                    int row = row0 + 8 * hh;
                    float v0 = acc[mt][nt][hh * 2 + 0] + b0;
                    float v1 = acc[mt][nt][hh * 2 + 1] + b1;
                    if (act) { v0 = gelu_f(v0); v1 = gelu_f(v1); }
                    if (res) {
                        float2 rr = *(const float2*)&res[(size_t)row * ldc + col];
                        v0 += rr.x; v1 += rr.y;
                    }
                    if (out_bf16) {
                        *(__nv_bfloat162*)&((__nv_bfloat16*)Cc)[(size_t)row * ldc + col] =
                            __float22bfloat162_rn(make_float2(v0, v1));
                    } else {
                        *(float2*)&((float*)Cc)[(size_t)row * ldc + col] =
                            make_float2(v0, v1);
                    }
                }
            }
        }
    }
}

// ---------------------------------------------------------------------------
// Windowed PSA attention.  One block per 8x8 window (2048 windows).
// 384 threads = 64 q-tokens x 6 heads; softmax over 16 kv fully in registers.
// Output written bf16 (feeds the proj GEMM).
// ---------------------------------------------------------------------------
__global__ __launch_bounds__(384) void attn_kernel(
    const float* __restrict__ qkv,
    const float* __restrict__ bias_table,
    __nv_bfloat16* __restrict__ aw)
{
    __shared__ float ks[16][192];
    __shared__ float vs[16][192];
    __shared__ float bt[296];
    int w  = blockIdx.x;
    int b  = w >> 10;
    int wi = w & 1023;
    int wy = wi >> 5, wx = wi & 31;
    int gbase = b*65536 + wy*2048 + wx*8;
    int tid = threadIdx.x;

    for (int i = tid; i < 294; i += 384) bt[i] = bias_table[i];
    for (int i = tid; i < 3072; i += 384) {
        int kt = i / 192, f = i - kt*192;
        int p0 = kt >> 2, p1 = kt & 3;
        int s0 = f / 96;
        int s1 = (f / 48) & 1;
        int c  = f % 48;
        int g  = gbase + (p0*2 + s0)*256 + (p1*2 + s1);
        const float* row = qkv + (size_t)g*QKVLD + 192;
        ks[kt][f] = row[c];
        vs[kt][f] = row[48 + c];
    }
    __syncthreads();

    int h  = tid / 64;
    int qt = tid - h*64;
    int qi = qt >> 3, qj = qt & 7;
    int g  = gbase + qi*256 + qj;
    const float* qp = qkv + (size_t)g*QKVLD + h*32;
    float q[32];
#pragma unroll
    for (int d = 0; d < 32; d += 4) {
        float4 t4 = *(const float4*)(qp + d);
        q[d]=t4.x*ATT_SCALE; q[d+1]=t4.y*ATT_SCALE;
        q[d+2]=t4.z*ATT_SCALE; q[d+3]=t4.w*ATT_SCALE;
    }
    float sc[16]; float mx = -1e30f;
    int rq0 = (qi >> 1) + 3, rq1 = (qj >> 1) + 3;
#pragma unroll
    for (int kt = 0; kt < 16; kt++) {
        const float* kr = &ks[kt][h*32];
        float s = 0.f;
#pragma unroll
        for (int d = 0; d < 32; d++) s += q[d]*kr[d];
        int rel = (rq0 - (kt >> 2))*7 + rq1 - (kt & 3);
        s += bt[rel*6 + h];
        sc[kt] = s;
        mx = fmaxf(mx, s);
    }
    float sum = 0.f;
#pragma unroll
    for (int kt = 0; kt < 16; kt++) { sc[kt] = __expf(sc[kt] - mx); sum += sc[kt]; }
    float inv = 1.f / sum;
    float o[32];
#pragma unroll
    for (int d = 0; d < 32; d++) o[d] = 0.f;
#pragma unroll
    for (int kt = 0; kt < 16; kt++) {
        float a = sc[kt]*inv;
        const float* vr = &vs[kt][h*32];
#pragma unroll
        for (int d = 0; d < 32; d++) o[d] += a*vr[d];
    }
    __nv_bfloat162* op = (__nv_bfloat162*)(aw + (size_t)g*192 + h*32);
#pragma unroll
    for (int d = 0; d < 32; d += 2)
        op[d >> 1] = __float22bfloat162_rn(make_float2(o[d], o[d+1]));
}

// ---------------------------------------------------------------------------
// Depthwise 5x5 conv (channel-last, bf16 in/out) + GELU + residual:
//   out = h1 + gelu(conv(h1) + dwb)
// ---------------------------------------------------------------------------
__global__ __launch_bounds__(256) void dwconv_kernel(
    const __nv_bfloat16* __restrict__ h1, const float* __restrict__ wk,
    const float* __restrict__ wb, __nv_bfloat16* __restrict__ out)
{
    __shared__ float ws[25][128];
    __shared__ float bs[128];
    int cb  = blockIdx.y * 128;
    int tid = threadIdx.x;
    for (int i = tid; i < 3200; i += 256) {
        int k = i >> 7, c = i & 127;
        ws[k][c] = wk[(size_t)(cb + c)*25 + k];
    }
    if (tid < 128) bs[tid] = wb[cb + tid];
    __syncthreads();

    int tl = tid >> 5;
    int cg = tid & 31;
    int token = blockIdx.x * 8 + tl;
    int b = token >> 16;
    int p = token & 65535;
    int y = p >> 8, x0 = p & 255;
    int ch = cb + cg*4;
    float4 acc    = make_float4(0.f, 0.f, 0.f, 0.f);
    float4 center = make_float4(0.f, 0.f, 0.f, 0.f);
#pragma unroll
    for (int dy = 0; dy < 5; dy++) {
        int yy = y + dy - 2;
        bool yok = (unsigned)yy < 256u;
#pragma unroll
        for (int dx = 0; dx < 5; dx++) {
            int xc = x0 + dx - 2;
            float4 v = make_float4(0.f, 0.f, 0.f, 0.f);
            if (yok && (unsigned)xc < 256u) {
                uint2 raw = *(const uint2*)&h1[((size_t)(b*65536 + yy*256 + xc))*HID + ch];
                float2 f0 = __bfloat1622float2(*reinterpret_cast<__nv_bfloat162*>(&raw.x));
                float2 f1 = __bfloat1622float2(*reinterpret_cast<__nv_bfloat162*>(&raw.y));
                v = make_float4(f0.x, f0.y, f1.x, f1.y);
            }
            if (dy == 2 && dx == 2) center = v;
            float4 wv = *(const float4*)&ws[dy*5 + dx][cg*4];
            acc.x += v.x*wv.x; acc.y += v.y*wv.y;
            acc.z += v.z*wv.z; acc.w += v.w*wv.w;
        }
    }
    float4 bb = *(const float4*)&bs[cg*4];
    float2 r0, r1;
    r0.x = center.x + gelu_f(acc.x + bb.x);
    r0.y = center.y + gelu_f(acc.y + bb.y);
    r1.x = center.z + gelu_f(acc.z + bb.z);
    r1.y = center.w + gelu_f(acc.w + bb.w);
    uint2 o;
    *reinterpret_cast<__nv_bfloat162*>(&o.x) = __float22bfloat162_rn(r0);
    *reinterpret_cast<__nv_bfloat162*>(&o.y) = __float22bfloat162_rn(r1);
    *(uint2*)&out[(size_t)token*HID + ch] = o;
}

// ---------------------------------------------------------------------------
// Launch sequence (graph-capturable: kernel launches only)
// ---------------------------------------------------------------------------
extern "C" void kernel_launch(void* const* d_in, const int* in_sizes, int n_in,
                              void* d_out, int out_size)
{
    const float* x    = (const float*)d_in[0];
    const float* g1   = (const float*)d_in[1];
    const float* be1  = (const float*)d_in[2];
    const float* wq   = (const float*)d_in[3];
    const float* bq   = (const float*)d_in[4];
    const float* wkv  = (const float*)d_in[5];
    const float* bkv  = (const float*)d_in[6];
    const float* btab = (const float*)d_in[7];
    const float* wproj= (const float*)d_in[8];
    const float* bproj= (const float*)d_in[9];
    const float* g2   = (const float*)d_in[10];
    const float* be2  = (const float*)d_in[11];
    const float* w1f  = (const float*)d_in[12];
    const float* b1f  = (const float*)d_in[13];
    const float* dwk  = (const float*)d_in[14];
    const float* dwb  = (const float*)d_in[15];
    const float* w2f  = (const float*)d_in[16];
    const float* b2f  = (const float*)d_in[17];
    float* out = (float*)d_out;

    __nv_bfloat16 *xn, *aw, *h1, *h, *wb;
    float *qkv, *x2;
    cudaGetSymbolAddress((void**)&xn,  g_xn);
    cudaGetSymbolAddress((void**)&qkv, g_qkv);
    cudaGetSymbolAddress((void**)&aw,  g_aw);
    cudaGetSymbolAddress((void**)&x2,  g_x2);
    cudaGetSymbolAddress((void**)&h1,  g_h1);
    cudaGetSymbolAddress((void**)&h,   g_h);
    cudaGetSymbolAddress((void**)&wb,  g_wb);

    // 0. Weight conversion to bf16 (cheap, inside the graph)
    f2b_kernel<<<(36864 + 255)/256, 256>>>(wq,    wb + WB_WQ,    36864);
    f2b_kernel<<<(18432 + 255)/256, 256>>>(wkv,   wb + WB_WKV,   18432);
    f2b_kernel<<<(36864 + 255)/256, 256>>>(wproj, wb + WB_WPROJ, 36864);
    f2b_kernel<<<(147456 + 255)/256, 256>>>(w1f,  wb + WB_W1F,   147456);
    f2b_kernel<<<(147456 + 255)/256, 256>>>(w2f,  wb + WB_W2F,   147456);

    // 1. LN1 -> xn (bf16)
    ln_kernel<<<NTOK/8, 256>>>(x, g1, be1, xn);
    // 2. Q = xn @ wq + bq  (fp32 into qkv cols [0,192), ldc=288)
    gemm_bf16_kernel<<<dim3(3, NTOK/128), 256>>>(xn, 192, wb + WB_WQ, 192, bq,
                                                 qkv, QKVLD, 192, 192,
                                                 nullptr, 0, 0);
    // 3. KV = xn @ wkv + bkv  (fp32 into qkv cols [192,288))
    gemm_bf16_kernel<<<dim3(2, NTOK/128), 256>>>(xn, 192, wb + WB_WKV, 96, bkv,
                                                 qkv + 192, QKVLD, 96, 192,
                                                 nullptr, 0, 0);
    // 4. Window attention -> aw (bf16, token order)
    attn_kernel<<<2048, 384>>>(qkv, btab, aw);
    // 5. x2 = aw @ wproj + bproj + x  (fp32)
    gemm_bf16_kernel<<<dim3(3, NTOK/128), 256>>>(aw, 192, wb + WB_WPROJ, 192, bproj,
                                                 x2, 192, 192, 192,
                                                 x, 0, 0);
    // 6. LN2 -> xn (bf16)
    ln_kernel<<<NTOK/8, 256>>>(x2, g2, be2, xn);
    // 7. h1 = gelu(xn @ w1f + b1f)  (bf16)
    gemm_bf16_kernel<<<dim3(12, NTOK/128), 256>>>(xn, 192, wb + WB_W1F, HID, b1f,
                                                  h1, HID, HID, 192,
                                                  nullptr, 1, 1);
    // 8. h = h1 + gelu(dwconv(h1) + dwb)  (bf16)
    dwconv_kernel<<<dim3(NTOK/8, 6), 256>>>(h1, dwk, dwb, h);
    // 9. out = h @ w2f + b2f + x2  (fp32)
    gemm_bf16_kernel<<<dim3(3, NTOK/128), 256>>>(h, HID, wb + WB_W2F, 192, b2f,
                                                 out, 192, 192, HID,
                                                 x2, 0, 0);
}